// round 2
// baseline (speedup 1.0000x reference)
#include <cuda_runtime.h>

#define NPTS 16384
#define NSP  4096
#define KNN  11
#define BT   128

// Monotone float->uint mapping (order-preserving for all finite floats)
__device__ __forceinline__ unsigned fkey(float f) {
    unsigned b = __float_as_uint(f);
    return b ^ ((unsigned)((int)b >> 31) | 0x80000000u);
}
__device__ __forceinline__ float funkey(unsigned u) {
    unsigned b = (u & 0x80000000u) ? (u ^ 0x80000000u) : ~u;
    return __uint_as_float(b);
}

// Sentinel: upper 32 = fkey(+inf) = 0xFF800000 (decodes back to +inf),
// lower 32 = all ones so any real (key,idx) with equal upper sorts first.
#define SENTINEL 0xFF800000FFFFFFFFull

__global__ void __launch_bounds__(BT) voro_kernel(
    const float* __restrict__ points,
    const float* __restrict__ spoints,
    float* __restrict__ out)
{
    extern __shared__ float4 ss[];   // NSP entries: (x, y, z, x^2+y^2+z^2)

    const int g = blockIdx.x * BT + threadIdx.x;   // global point id
    const int b = g / NPTS;                        // batch (uniform per block: BT | NPTS)

    // Stage this batch's spoints into shared memory with precomputed |s|^2.
    const float* sp = spoints + (size_t)b * NSP * 3;
    for (int j = threadIdx.x; j < NSP; j += BT) {
        float x = sp[3 * j + 0];
        float y = sp[3 * j + 1];
        float z = sp[3 * j + 2];
        ss[j] = make_float4(x, y, z, fmaf(x, x, fmaf(y, y, z * z)));
    }
    __syncthreads();

    const float* pp = points + (size_t)g * 3;
    const float px = pp[0], py = pp[1], pz = pp[2];
    const float p2 = fmaf(px, px, fmaf(py, py, pz * pz));

    // Sorted ascending top-11 of (dist_key << 32 | idx).
    unsigned long long best[KNN];
#pragma unroll
    for (int k = 0; k < KNN; ++k) best[k] = SENTINEL;
    float worst = __int_as_float(0x7f800000);  // +inf

#pragma unroll 4
    for (int j = 0; j < NSP; ++j) {
        float4 s = ss[j];
        float t  = fmaf(px, s.x, fmaf(py, s.y, pz * s.z));
        // Same expansion as reference: |p|^2 + |s|^2 - 2 p.s
        float d2 = fmaf(-2.0f, t, p2 + s.w);
        if (d2 <= worst) {                      // fast reject (vast majority)
            unsigned long long key =
                ((unsigned long long)fkey(d2) << 32) | (unsigned)j;
            if (key < best[KNN - 1]) {
                best[KNN - 1] = key;
#pragma unroll
                for (int k = KNN - 1; k > 0; --k) {
                    if (best[k] < best[k - 1]) {
                        unsigned long long tmp = best[k];
                        best[k] = best[k - 1];
                        best[k - 1] = tmp;
                    }
                }
                worst = funkey((unsigned)(best[KNN - 1] >> 32));
            }
        }
    }

    // Epilogue: Voronoi edge half-plane distances, min over the 10 edges.
    // sq = (dot(v,e)/|e| - |e|/2)^2 == (dot(v,e) - |e|^2/2)^2 / |e|^2
    float4 c = ss[(unsigned)best[0] & 0xFFFu];
    float vx = px - c.x, vy = py - c.y, vz = pz - c.z;
    float m = __int_as_float(0x7f800000);
#pragma unroll
    for (int k = 1; k < KNN; ++k) {
        float4 sk = ss[(unsigned)best[k] & 0xFFFu];
        float ex = sk.x - c.x, ey = sk.y - c.y, ez = sk.z - c.z;
        float el2 = fmaf(ex, ex, fmaf(ey, ey, ez * ez));
        float dve = fmaf(vx, ex, fmaf(vy, ey, vz * ez));
        float u   = fmaf(-0.5f, el2, dve);
        m = fminf(m, (u * u) / el2);
    }
    out[g] = m;
}

extern "C" void kernel_launch(void* const* d_in, const int* in_sizes, int n_in,
                              void* d_out, int out_size) {
    const float* points  = (const float*)d_in[0];   // (2, 16384, 3) f32
    const float* spoints = (const float*)d_in[1];   // (2, 4096, 3)  f32
    float* out = (float*)d_out;                     // (2, 16384)    f32

    const size_t smem = NSP * sizeof(float4);       // 64 KB > 48 KB static limit
    cudaFuncSetAttribute(voro_kernel,
                         cudaFuncAttributeMaxDynamicSharedMemorySize, (int)smem);
    voro_kernel<<<(2 * NPTS) / BT, BT, smem>>>(points, spoints, out);
}